// round 3
// baseline (speedup 1.0000x reference)
#include <cuda_runtime.h>

// 4-qubit statevector VQC, one warp, lane l (mod 16) = amplitude index l
// (qubit n <-> bit 8>>n).
//
// R3 changes vs R2:
//  * gate matrices built DISTRIBUTED (lane g builds gate g) and staged in
//    smem as float4 -> the amplitude loop is 1 LDS.128 + 2 SHFL + 8 FMA per
//    gate, nothing else on the dependency chain.
//  * RX(psi) data encoding folded into the initial product state
//    (still a product state) -> 40 shuffle-gate steps instead of 44.
//  * CNOT ring composed into one permutation, fused into the qubit-0 gate's
//    variable-source shuffle (unchanged from R2, verified).

__global__ void __launch_bounds__(32, 1)
vqc_kernel(const float* __restrict__ psi,
           const float* __restrict__ ring,
           const float* __restrict__ prx,
           const float* __restrict__ pry,
           const float* __restrict__ prz,
           float* __restrict__ out) {
    __shared__ float4 Gs[40];   // per gate: (g00re, g00im, g01re, g01im)
    __shared__ float2 Ps[4];    // per qubit: (cos(psi/2), sin(psi/2))
    const unsigned FULL = 0xFFFFFFFFu;
    const int l = threadIdx.x;

    // ---- distributed build: lane idx builds gate idx (fused M = RZ*RY*RX) ----
#pragma unroll
    for (int t = 0; t < 2; t++) {
        int idx = l + t * 32;
        if (idx < 40) {
            float c1, s1, c2, s2, c3, s3;
            __sincosf(0.5f * prx[idx], &s1, &c1);
            __sincosf(0.5f * pry[idx], &s2, &c2);
            __sincosf(0.5f * prz[idx], &s3, &c3);
            float p1 = c2 * c1, p2 = s2 * s1, p3 = s2 * c1, p4 = c2 * s1;
            float g00re =  fmaf(c3, p1,  s3 * p2);
            float g00im =  fmaf(c3, p2, -s3 * p1);
            float g01re = -fmaf(c3, p3,  s3 * p4);
            float g01im =  fmaf(s3, p3, -c3 * p4);
            Gs[idx] = make_float4(g00re, g00im, g01re, g01im);
        } else if (t == 1 && l >= 8 && l < 12) {
            float s, c;
            __sincosf(0.5f * psi[l - 8], &s, &c);
            Ps[l - 8] = make_float2(c, s);
        }
    }
    __syncwarp();

    // ---- initial state with RX(psi) folded in (still a product state) ----
    // v_n[b] = RX(psi_n) . ring_n  =  ( c_n*ring[n][b],  -s_n*ring[n][b^1] )
    float4 rA = reinterpret_cast<const float4*>(ring)[0];
    float4 rB = reinterpret_cast<const float4*>(ring)[1];
    float rr[4][2] = { { rA.x, rA.y }, { rA.z, rA.w },
                       { rB.x, rB.y }, { rB.z, rB.w } };
    float re, im;
    {
        float vre[4], vim[4];
#pragma unroll
        for (int n = 0; n < 4; n++) {
            int b = (l >> (3 - n)) & 1;
            float2 cs = Ps[n];
            vre[n] =  cs.x * rr[n][b];
            vim[n] = -cs.y * rr[n][b ^ 1];
        }
        float are = vre[0] * vre[1] - vim[0] * vim[1];
        float aim = vre[0] * vim[1] + vim[0] * vre[1];
        float bre = vre[2] * vre[3] - vim[2] * vim[3];
        float bim = vre[2] * vim[3] + vim[2] * vre[3];
        re = are * bre - aim * bim;
        im = are * bim + aim * bre;
    }

    // per-lane sign per qubit: -1 if this lane's bit for qubit n is set
    float sb[4];
#pragma unroll
    for (int n = 0; n < 4; n++) sb[n] = (l & (8 >> n)) ? -1.0f : 1.0f;

    // ---- CNOT ring (8,4)(4,2)(2,1)(1,8) composed into one permutation ----
    auto perm = [](int j) {
        j = (j & 1) ? (j ^ 8) : j;
        j = (j & 2) ? (j ^ 1) : j;
        j = (j & 4) ? (j ^ 2) : j;
        j = (j & 8) ? (j ^ 4) : j;
        return j;
    };
    const int src_self = perm(l);
    const int src_part = perm(l ^ 8);

    // ---- variational layers: 1 LDS.128 + 2 SHFL + 8 FMA per gate ----
#pragma unroll
    for (int d = 0; d < 10; d++) {
#pragma unroll
        for (int n = 0; n < 4; n++) {
            float4 g = Gs[d * 4 + n];
            float Pim = sb[n] * g.y;   // lane-bit ? g11.im : g00.im
            float Qre = sb[n] * g.z;   // lane-bit ? g10.re : g01.re

            float ore, oim, pre, pim;
            if (n == 0) {
                // CNOT permutation fused into this gate's shuffles
                ore = __shfl_sync(FULL, re, src_self);
                oim = __shfl_sync(FULL, im, src_self);
                pre = __shfl_sync(FULL, re, src_part);
                pim = __shfl_sync(FULL, im, src_part);
            } else {
                ore = re; oim = im;
                pre = __shfl_xor_sync(FULL, re, 8 >> n);
                pim = __shfl_xor_sync(FULL, im, 8 >> n);
            }

            float nre = g.x * ore;
            nre = fmaf(-Pim, oim, nre);
            nre = fmaf( Qre, pre, nre);
            nre = fmaf(-g.w, pim, nre);
            float nim = g.x * oim;
            nim = fmaf( Pim, ore, nim);
            nim = fmaf( Qre, pim, nim);
            nim = fmaf( g.w, pre, nim);
            re = nre; im = nim;
        }
    }

    // ---- outputs: |amp[0]|^2, |amp[2]|^2, |amp[15]|^2 ----
    float prob = fmaf(re, re, im * im);
    if (l == 0)       out[0] = prob;
    else if (l == 2)  out[1] = prob;
    else if (l == 15) out[2] = prob;
}

extern "C" void kernel_launch(void* const* d_in, const int* in_sizes, int n_in,
                              void* d_out, int out_size) {
    const float* psi  = (const float*)d_in[0];
    const float* ring = (const float*)d_in[1];
    const float* prx  = (const float*)d_in[2];
    const float* pry  = (const float*)d_in[3];
    const float* prz  = (const float*)d_in[4];
    vqc_kernel<<<1, 32>>>(psi, ring, prx, pry, prz, (float*)d_out);
}

// round 4
// speedup vs baseline: 1.0385x; 1.0385x over previous
#include <cuda_runtime.h>

// 4-qubit statevector VQC, one warp, lane k=l&15 holds amplitude index k
// (qubit n <-> bit 8>>n).
//
// R4: each layer = Pσ (composed CNOT ring, fused into gather sources), then
// a 4x4 pair-gate on qubits (0,1), then a 4x4 pair-gate on qubits (2,3).
// Dependent chain: 20 gather-steps total (was 40). Pair matrices are built
// distributed in the prologue and staged in smem (2 x float4 per row).

__global__ void __launch_bounds__(32, 1)
vqc_kernel(const float* __restrict__ psi,
           const float* __restrict__ ring,
           const float* __restrict__ prx,
           const float* __restrict__ pry,
           const float* __restrict__ prz,
           float* __restrict__ out) {
    __shared__ float4 Gs[40];      // fused 2x2 per gate: (g00re,g00im,g01re,g01im)
    __shared__ float4 Rows[160];   // 80 pair-matrix rows x 2 float4
    __shared__ float2 Ps[4];       // (cos(psi/2), sin(psi/2))
    const unsigned FULL = 0xFFFFFFFFu;
    const int l = threadIdx.x;
    const int k = l & 15;

    // ---- stage 1: fused 2x2 gates M = RZ*RY*RX, distributed ----
#pragma unroll
    for (int t = 0; t < 2; t++) {
        int idx = l + t * 32;
        if (idx < 40) {
            float c1, s1, c2, s2, c3, s3;
            __sincosf(0.5f * prx[idx], &s1, &c1);
            __sincosf(0.5f * pry[idx], &s2, &c2);
            __sincosf(0.5f * prz[idx], &s3, &c3);
            float p1 = c2 * c1, p2 = s2 * s1, p3 = s2 * c1, p4 = c2 * s1;
            float g00re =  fmaf(c3, p1,  s3 * p2);
            float g00im =  fmaf(c3, p2, -s3 * p1);
            float g01re = -fmaf(c3, p3,  s3 * p4);
            float g01im =  fmaf(s3, p3, -c3 * p4);
            Gs[idx] = make_float4(g00re, g00im, g01re, g01im);
        } else if (t == 1 && l >= 8 && l < 12) {
            float s, c;
            __sincosf(0.5f * psi[l - 8], &s, &c);
            Ps[l - 8] = make_float2(c, s);
        }
    }
    __syncwarp();

    // ---- stage 2: 4x4 pair matrices G = M_{2p} (x) M_{2p+1}, distributed ----
    // row index: idx = d*8 + p*4 + r, r=(a,b); entries j=(c,dd).
#pragma unroll
    for (int t = 0; t < 3; t++) {
        int idx = l + t * 32;
        if (idx < 80) {
            int d = idx >> 3, w = idx & 7, p = w >> 2, r = w & 3;
            int a = r >> 1, b = r & 1;
            float4 gA = Gs[d * 4 + 2 * p];
            float4 gB = Gs[d * 4 + 2 * p + 1];
            // row a of M: a==0 -> (g00,g01); a==1 -> (-conj(g01), conj(g00))
            float ar0 = a ? -gA.z : gA.x, ai0 = a ?  gA.w : gA.y;
            float ar1 = a ?  gA.x : gA.z, ai1 = a ? -gA.y : gA.w;
            float br0 = b ? -gB.z : gB.x, bi0 = b ?  gB.w : gB.y;
            float br1 = b ?  gB.x : gB.z, bi1 = b ? -gB.y : gB.w;
            // G[j] = Arow[c] * Brow[dd], j = c*2+dd
            float g0r = ar0 * br0 - ai0 * bi0, g0i = ar0 * bi0 + ai0 * br0;
            float g1r = ar0 * br1 - ai0 * bi1, g1i = ar0 * bi1 + ai0 * br1;
            float g2r = ar1 * br0 - ai1 * bi0, g2i = ar1 * bi0 + ai1 * br0;
            float g3r = ar1 * br1 - ai1 * bi1, g3i = ar1 * bi1 + ai1 * br1;
            Rows[idx * 2 + 0] = make_float4(g0r, g0i, g1r, g1i);
            Rows[idx * 2 + 1] = make_float4(g2r, g2i, g3r, g3i);
        }
    }
    __syncwarp();

    // ---- initial product state with RX(psi) folded in ----
    float4 rA4 = reinterpret_cast<const float4*>(ring)[0];
    float4 rB4 = reinterpret_cast<const float4*>(ring)[1];
    float rr[4][2] = { { rA4.x, rA4.y }, { rA4.z, rA4.w },
                       { rB4.x, rB4.y }, { rB4.z, rB4.w } };
    float re, im;
    {
        float vre[4], vim[4];
#pragma unroll
        for (int n = 0; n < 4; n++) {
            int b = (k >> (3 - n)) & 1;
            float2 cs = Ps[n];
            vre[n] =  cs.x * rr[n][b];
            vim[n] = -cs.y * rr[n][b ^ 1];
        }
        float are = vre[0] * vre[1] - vim[0] * vim[1];
        float aim = vre[0] * vim[1] + vim[0] * vre[1];
        float bre = vre[2] * vre[3] - vim[2] * vim[3];
        float bim = vre[2] * vim[3] + vim[2] * vre[3];
        re = are * bre - aim * bim;
        im = are * bim + aim * bre;
    }

    // ---- composed CNOT-ring permutation (verified R2/R3) ----
    auto perm = [](int j) {
        j = (j & 1) ? (j ^ 8) : j;
        j = (j & 2) ? (j ^ 1) : j;
        j = (j & 4) ? (j ^ 2) : j;
        j = (j & 8) ? (j ^ 4) : j;
        return j;
    };
    // step A (pair 0, bits 8,4) gathers through sigma; step B plain.
    int sA0 = perm((k & 3) | 0), sA1 = perm((k & 3) | 4);
    int sA2 = perm((k & 3) | 8), sA3 = perm((k & 3) | 12);
    int sB0 = (k & 12) | 0, sB1 = (k & 12) | 1;
    int sB2 = (k & 12) | 2, sB3 = (k & 12) | 3;
    const int rA = (k >> 2) & 3, rB = k & 3;

    // ---- variational layers: 2 gather-steps per layer ----
#pragma unroll
    for (int d = 0; d < 10; d++) {
        {   // step A: sigma-fused 4x4 on qubits (0,1)
            int base = (d * 8 + rA) * 2;
            float4 e0 = Rows[base], e1 = Rows[base + 1];
            float x0 = __shfl_sync(FULL, re, sA0), y0 = __shfl_sync(FULL, im, sA0);
            float x1 = __shfl_sync(FULL, re, sA1), y1 = __shfl_sync(FULL, im, sA1);
            float x2 = __shfl_sync(FULL, re, sA2), y2 = __shfl_sync(FULL, im, sA2);
            float x3 = __shfl_sync(FULL, re, sA3), y3 = __shfl_sync(FULL, im, sA3);
            float pr0 = e0.x * x0; pr0 = fmaf(-e0.y, y0, pr0);
            float pr1 = e0.z * x1; pr1 = fmaf(-e0.w, y1, pr1);
            float pr2 = e1.x * x2; pr2 = fmaf(-e1.y, y2, pr2);
            float pr3 = e1.z * x3; pr3 = fmaf(-e1.w, y3, pr3);
            float pi0 = e0.x * y0; pi0 = fmaf(e0.y, x0, pi0);
            float pi1 = e0.z * y1; pi1 = fmaf(e0.w, x1, pi1);
            float pi2 = e1.x * y2; pi2 = fmaf(e1.y, x2, pi2);
            float pi3 = e1.z * y3; pi3 = fmaf(e1.w, x3, pi3);
            re = (pr0 + pr1) + (pr2 + pr3);
            im = (pi0 + pi1) + (pi2 + pi3);
        }
        {   // step B: 4x4 on qubits (2,3)
            int base = (d * 8 + 4 + rB) * 2;
            float4 e0 = Rows[base], e1 = Rows[base + 1];
            float x0 = __shfl_sync(FULL, re, sB0), y0 = __shfl_sync(FULL, im, sB0);
            float x1 = __shfl_sync(FULL, re, sB1), y1 = __shfl_sync(FULL, im, sB1);
            float x2 = __shfl_sync(FULL, re, sB2), y2 = __shfl_sync(FULL, im, sB2);
            float x3 = __shfl_sync(FULL, re, sB3), y3 = __shfl_sync(FULL, im, sB3);
            float pr0 = e0.x * x0; pr0 = fmaf(-e0.y, y0, pr0);
            float pr1 = e0.z * x1; pr1 = fmaf(-e0.w, y1, pr1);
            float pr2 = e1.x * x2; pr2 = fmaf(-e1.y, y2, pr2);
            float pr3 = e1.z * x3; pr3 = fmaf(-e1.w, y3, pr3);
            float pi0 = e0.x * y0; pi0 = fmaf(e0.y, x0, pi0);
            float pi1 = e0.z * y1; pi1 = fmaf(e0.w, x1, pi1);
            float pi2 = e1.x * y2; pi2 = fmaf(e1.y, x2, pi2);
            float pi3 = e1.z * y3; pi3 = fmaf(e1.w, x3, pi3);
            re = (pr0 + pr1) + (pr2 + pr3);
            im = (pi0 + pi1) + (pi2 + pi3);
        }
    }

    // ---- outputs: |amp[0]|^2, |amp[2]|^2, |amp[15]|^2 ----
    float prob = fmaf(re, re, im * im);
    if (l == 0)       out[0] = prob;
    else if (l == 2)  out[1] = prob;
    else if (l == 15) out[2] = prob;
}

extern "C" void kernel_launch(void* const* d_in, const int* in_sizes, int n_in,
                              void* d_out, int out_size) {
    const float* psi  = (const float*)d_in[0];
    const float* ring = (const float*)d_in[1];
    const float* prx  = (const float*)d_in[2];
    const float* pry  = (const float*)d_in[3];
    const float* prz  = (const float*)d_in[4];
    vqc_kernel<<<1, 32>>>(psi, ring, prx, pry, prz, (float*)d_out);
}